// round 3
// baseline (speedup 1.0000x reference)
#include <cuda_runtime.h>
#include <cstdint>
#include <cstddef>

#define NB 8
#define NL 512
#define ND 512
#define NH 8
#define HD 64
#define NE 4
#define NDF 2048
#define NBL 4096   // NB*NL

#define NEGINF __int_as_float(0xff800000)

typedef unsigned long long ull;

// packed fp32x2 FMA (Blackwell FFMA2) — only reachable via PTX
__device__ __forceinline__ void ffma2(ull& d, ull a, ull b) {
    asm("fma.rn.f32x2 %0, %1, %2, %0;" : "+l"(d) : "l"(a), "l"(b));
}
__device__ __forceinline__ float2 up2(ull v) {
    float2 f;
    asm("mov.b64 {%0, %1}, %2;" : "=f"(f.x), "=f"(f.y) : "l"(v));
    return f;
}

// ---------------- scratch (static device allocations) ----------------
__device__ float g_h [NBL*ND];
__device__ float g_t [NBL*ND];
__device__ float g_q [NBL*ND];
__device__ float g_k [NBL*ND];
__device__ float g_v [NBL*ND];
__device__ float g_ao[NBL*ND];
__device__ float g_mid[NBL*NDF];
__device__ float g_sc[(size_t)64*NL*NL];     // [B*H][L][L]
__device__ float g_cw[NE*3*ND*ND];           // conv weights transposed [l][k][i][o]

// ---------------- conv weight transpose: w[l][o][i][k] -> w2[l][k][i][o] ----------------
__global__ void tconv_kernel(const float* __restrict__ w, float* __restrict__ o) {
    int idx = blockIdx.x * 256 + threadIdx.x;        // total 4*3*512*512
    int l  = idx / (3*ND*ND);
    int r  = idx % (3*ND*ND);
    int k  = r / (ND*ND);
    int r2 = r % (ND*ND);
    int i  = r2 / ND;
    int oo = r2 % ND;
    o[idx] = w[(((size_t)l*ND + oo)*ND + i)*3 + k];
}

// ---------------- input embedding ----------------
__global__ __launch_bounds__(256) void embed_kernel(
    const float* __restrict__ x, const float* __restrict__ tf,
    const float* __restrict__ inw, const float* __restrict__ inb,
    const float* __restrict__ pe, const float* __restrict__ tw,
    const float* __restrict__ tb, const float* __restrict__ ps,
    const float* __restrict__ ts, float* __restrict__ out)
{
    int bl = blockIdx.x;
    int t  = threadIdx.x;
    __shared__ float xs[64];
    __shared__ float t2[2];
    if (t < 64) xs[t] = x[bl*64 + t];
    if (t < 2)  t2[t] = tf[bl*2 + t];
    __syncthreads();
    float pss = ps[0], tss = ts[0];
    int pos = bl & (NL-1);
    #pragma unroll
    for (int rep = 0; rep < 2; rep++) {
        int d = t + (rep << 8);
        float acc = inb[d];
        #pragma unroll 16
        for (int i = 0; i < 64; i++) acc += xs[i] * inw[i*ND + d];
        acc += pss * pe[pos*ND + d];
        acc += tss * (t2[0]*tw[d] + t2[1]*tw[ND + d] + tb[d]);
        out[bl*ND + d] = acc;
    }
}

// ---------------- SGEMM 128x128x16, double-buffered, 8x8 per thread, FFMA2 ----------------
// A values stored DUPLICATED in smem so the broadcast operand loads as an f32x2 pair.
// C[m,n] = sum_k A[m,k]*B[k,n] + bias[n]  (+relu) (+res[m,n])
// CONV: A addressing becomes causal-conv gather (taps along K: k = tap*512 + chan)
template<int CONV, int RELU, int ADDRES>
__device__ __forceinline__ void gemm_body(
    const float* __restrict__ A, const float* __restrict__ Bm,
    const float* __restrict__ bias, const float* __restrict__ res,
    float* __restrict__ C, int N, int K, int bn, int bm)
{
    __shared__ __align__(16) float As[2][16][256];   // duplicated pairs: [k][2m],[2m+1]
    __shared__ __align__(16) float Bs[2][16][128];

    int t  = threadIdx.x;
    int tx = t & 15, ty = t >> 4;

    int ar = t >> 2;             // 0..63  (A tile row within 64-row half)
    int ac = (t & 3) << 2;       // 0,4,8,12
    int br = t >> 5;             // 0..7
    int bc = (t & 31) << 2;      // 0..124

    float4 pa0, pa1, pb0, pb1;

    #define LOAD_A(k0, rowoff, dst)                                            \
        do {                                                                   \
            int m_ = bm + ar + (rowoff);                                       \
            if (CONV) {                                                        \
                int kk_ = (k0) + ac;                                           \
                int kidx_ = kk_ >> 9;                                          \
                int ii_ = kk_ & 511;                                           \
                int sh_ = kidx_ - 2;                                           \
                int tt_ = m_ & 511;                                            \
                if (tt_ + sh_ >= 0)                                            \
                    dst = *(const float4*)&A[(size_t)(m_ + sh_)*512 + ii_];    \
                else dst = make_float4(0.f, 0.f, 0.f, 0.f);                    \
            } else {                                                           \
                dst = *(const float4*)&A[(size_t)m_*K + (k0) + ac];            \
            }                                                                  \
        } while (0)

    #define STORE_AB(buf)                                                      \
        do {                                                                   \
            As[buf][ac+0][2*ar]      = pa0.x; As[buf][ac+0][2*ar+1]      = pa0.x; \
            As[buf][ac+1][2*ar]      = pa0.y; As[buf][ac+1][2*ar+1]      = pa0.y; \
            As[buf][ac+2][2*ar]      = pa0.z; As[buf][ac+2][2*ar+1]      = pa0.z; \
            As[buf][ac+3][2*ar]      = pa0.w; As[buf][ac+3][2*ar+1]      = pa0.w; \
            As[buf][ac+0][2*(ar+64)] = pa1.x; As[buf][ac+0][2*(ar+64)+1] = pa1.x; \
            As[buf][ac+1][2*(ar+64)] = pa1.y; As[buf][ac+1][2*(ar+64)+1] = pa1.y; \
            As[buf][ac+2][2*(ar+64)] = pa1.z; As[buf][ac+2][2*(ar+64)+1] = pa1.z; \
            As[buf][ac+3][2*(ar+64)] = pa1.w; As[buf][ac+3][2*(ar+64)+1] = pa1.w; \
            *(float4*)&Bs[buf][br][bc]   = pb0;                                \
            *(float4*)&Bs[buf][br+8][bc] = pb1;                                \
        } while (0)

    // prologue: tile 0 into buffer 0
    LOAD_A(0, 0, pa0);
    LOAD_A(0, 64, pa1);
    pb0 = *(const float4*)&Bm[(size_t)br*N + bn + bc];
    pb1 = *(const float4*)&Bm[(size_t)(br+8)*N + bn + bc];
    STORE_AB(0);
    __syncthreads();

    ull acc2[8][4];
    #pragma unroll
    for (int i = 0; i < 8; i++)
        #pragma unroll
        for (int j = 0; j < 4; j++) acc2[i][j] = 0ull;

    int nk = K >> 4;
    int cur = 0;

    for (int kt = 0; kt < nk; kt++) {
        if (kt + 1 < nk) {
            int k0 = (kt + 1) << 4;
            LOAD_A(k0, 0, pa0);
            LOAD_A(k0, 64, pa1);
            pb0 = *(const float4*)&Bm[(size_t)(k0 + br)*N + bn + bc];
            pb1 = *(const float4*)&Bm[(size_t)(k0 + br + 8)*N + bn + bc];
        }
        #pragma unroll
        for (int k = 0; k < 16; k++) {
            ulonglong2 a01 = *(const ulonglong2*)&As[cur][k][(ty << 4)];
            ulonglong2 a23 = *(const ulonglong2*)&As[cur][k][(ty << 4) + 4];
            ulonglong2 a45 = *(const ulonglong2*)&As[cur][k][(ty << 4) + 8];
            ulonglong2 a67 = *(const ulonglong2*)&As[cur][k][(ty << 4) + 12];
            ulonglong2 b03 = *(const ulonglong2*)&Bs[cur][k][(tx << 3)];
            ulonglong2 b47 = *(const ulonglong2*)&Bs[cur][k][(tx << 3) + 4];
            ull a2[8] = {a01.x, a01.y, a23.x, a23.y, a45.x, a45.y, a67.x, a67.y};
            ull b2[4] = {b03.x, b03.y, b47.x, b47.y};
            #pragma unroll
            for (int i = 0; i < 8; i++)
                #pragma unroll
                for (int j = 0; j < 4; j++)
                    ffma2(acc2[i][j], a2[i], b2[j]);
        }
        if (kt + 1 < nk) {
            int nx = cur ^ 1;
            STORE_AB(nx);
        }
        __syncthreads();
        cur ^= 1;
    }
    #undef LOAD_A
    #undef STORE_AB

    // epilogue
    float bb[8];
    *(float4*)&bb[0] = *(const float4*)&bias[bn + (tx << 3)];
    *(float4*)&bb[4] = *(const float4*)&bias[bn + (tx << 3) + 4];
    #pragma unroll
    for (int i = 0; i < 8; i++) {
        int row = bm + (ty << 3) + i;
        float o[8];
        #pragma unroll
        for (int j = 0; j < 4; j++) {
            float2 p = up2(acc2[i][j]);
            o[2*j]   = p.x + bb[2*j];
            o[2*j+1] = p.y + bb[2*j+1];
        }
        if (RELU) {
            #pragma unroll
            for (int j = 0; j < 8; j++) o[j] = fmaxf(o[j], 0.f);
        }
        if (ADDRES) {
            float4 r0 = *(const float4*)&res[(size_t)row*N + bn + (tx << 3)];
            float4 r1 = *(const float4*)&res[(size_t)row*N + bn + (tx << 3) + 4];
            o[0] += r0.x; o[1] += r0.y; o[2] += r0.z; o[3] += r0.w;
            o[4] += r1.x; o[5] += r1.y; o[6] += r1.z; o[7] += r1.w;
        }
        *(float4*)&C[(size_t)row*N + bn + (tx << 3)]     = *(float4*)&o[0];
        *(float4*)&C[(size_t)row*N + bn + (tx << 3) + 4] = *(float4*)&o[4];
    }
}

template<int CONV, int RELU, int ADDRES>
__global__ __launch_bounds__(256) void gemm_kernel(
    const float* __restrict__ A, const float* __restrict__ Bm,
    const float* __restrict__ bias, const float* __restrict__ res,
    float* __restrict__ C, int N, int K)
{
    gemm_body<CONV, RELU, ADDRES>(A, Bm, bias, res, C, N, K,
                                  blockIdx.x << 7, blockIdx.y << 7);
}

// merged Q/K/V projection: blockIdx.z selects the weight/bias/output set
__global__ __launch_bounds__(256) void gemm_qkv_kernel(
    const float* __restrict__ A,
    const float* __restrict__ w0, const float* __restrict__ w1, const float* __restrict__ w2,
    const float* __restrict__ b0, const float* __restrict__ b1, const float* __restrict__ b2,
    float* __restrict__ c0, float* __restrict__ c1, float* __restrict__ c2)
{
    int z = blockIdx.z;
    const float* w = (z == 0) ? w0 : (z == 1) ? w1 : w2;
    const float* b = (z == 0) ? b0 : (z == 1) ? b1 : b2;
    float*       c = (z == 0) ? c0 : (z == 1) ? c1 : c2;
    gemm_body<0, 0, 0>(A, w, b, nullptr, c, ND, ND,
                       blockIdx.x << 7, blockIdx.y << 7);
}

// ---------------- fused add + LayerNorm ----------------
__global__ __launch_bounds__(256) void ln_kernel(
    const float* __restrict__ a, const float* __restrict__ b,
    const float* __restrict__ sc, const float* __restrict__ bi,
    float* __restrict__ out)
{
    int row = blockIdx.x;
    int t = threadIdx.x;
    const float* ar = a + (size_t)row*ND;
    const float* br = b + (size_t)row*ND;
    float v0 = ar[t]       + br[t];
    float v1 = ar[t + 256] + br[t + 256];
    float s1 = v0 + v1;
    float s2 = v0*v0 + v1*v1;
    #pragma unroll
    for (int off = 16; off > 0; off >>= 1) {
        s1 += __shfl_xor_sync(0xffffffffu, s1, off);
        s2 += __shfl_xor_sync(0xffffffffu, s2, off);
    }
    __shared__ float r1[8], r2[8], mv[2];
    int w = t >> 5, lane = t & 31;
    if (lane == 0) { r1[w] = s1; r2[w] = s2; }
    __syncthreads();
    if (t == 0) {
        float a1 = 0.f, a2 = 0.f;
        #pragma unroll
        for (int i = 0; i < 8; i++) { a1 += r1[i]; a2 += r2[i]; }
        float mean = a1 * (1.f/512.f);
        float var  = a2 * (1.f/512.f) - mean*mean;
        mv[0] = mean;
        mv[1] = rsqrtf(var + 1e-5f);
    }
    __syncthreads();
    float mean = mv[0], rstd = mv[1];
    out[(size_t)row*ND + t]       = (v0 - mean)*rstd*sc[t]       + bi[t];
    out[(size_t)row*ND + t + 256] = (v1 - mean)*rstd*sc[t + 256] + bi[t + 256];
}

// ---------------- scores: per (b,h), lower-triangular 64x64 tiles of q @ k^T * scale --------
// FFMA2 packing over the d (reduction) axis; horizontal add at the end.
__global__ __launch_bounds__(256) void scores_kernel(
    const float* __restrict__ q, const float* __restrict__ k, float* __restrict__ sc)
{
    int nt = blockIdx.x, mt = blockIdx.y, bh = blockIdx.z;
    if (nt > mt) return;
    int b = bh >> 3, h = bh & 7;
    __shared__ __align__(16) float Qs[64*66];
    __shared__ __align__(16) float Ks[64*66];
    int t = threadIdx.x;
    const float* qb = q + ((size_t)(b*NL + mt*64))*ND + h*HD;
    const float* kb = k + ((size_t)(b*NL + nt*64))*ND + h*HD;
    #pragma unroll
    for (int i = 0; i < 16; i++) {
        int lin = t + (i << 8);
        int r = lin >> 6, d = lin & 63;
        Qs[r*66 + d] = qb[(size_t)r*ND + d];
        Ks[r*66 + d] = kb[(size_t)r*ND + d];
    }
    __syncthreads();
    int tx = t & 15, ty = t >> 4;
    ull acc2[4][4];
    #pragma unroll
    for (int i = 0; i < 4; i++)
        #pragma unroll
        for (int j = 0; j < 4; j++) acc2[i][j] = 0ull;

    #pragma unroll 8
    for (int d = 0; d < 64; d += 2) {
        ull a2[4], b2[4];
        #pragma unroll
        for (int i = 0; i < 4; i++) a2[i] = *(const ull*)&Qs[((ty<<2)+i)*66 + d];
        #pragma unroll
        for (int j = 0; j < 4; j++) b2[j] = *(const ull*)&Ks[((tx<<2)+j)*66 + d];
        #pragma unroll
        for (int i = 0; i < 4; i++)
            #pragma unroll
            for (int j = 0; j < 4; j++)
                ffma2(acc2[i][j], a2[i], b2[j]);
    }
    float* base = sc + (size_t)bh*NL*NL;
    #pragma unroll
    for (int i = 0; i < 4; i++) {
        int m = mt*64 + (ty<<2) + i;
        float o[4];
        #pragma unroll
        for (int j = 0; j < 4; j++) {
            float2 p = up2(acc2[i][j]);
            o[j] = (p.x + p.y) * 0.125f;
        }
        *(float4*)&base[(size_t)m*NL + nt*64 + (tx<<2)] = *(float4*)&o[0];
    }
}

// ---------------- top-k(256) select + softmax + P@V -----------------
// block = (qtile of 32 rows, bh). 256 threads, 8 warps, each warp owns 4 rows.
// dyn smem: p[32][512] (64KB) + vt[64][64] (16KB) = 80KB
__global__ __launch_bounds__(256) void attn_kernel(
    const float* __restrict__ sc, const float* __restrict__ v, float* __restrict__ ao)
{
    extern __shared__ float sm[];
    float* p  = sm;             // 32*512
    float* vt = sm + 32*512;    // 64*64
    int qt = blockIdx.x, bh = blockIdx.y;
    int b = bh >> 3, h = bh & 7;
    int t = threadIdx.x;

    // load 32 score rows
    const float4* s4 = (const float4*)(sc + (size_t)bh*NL*NL + (size_t)(qt*32)*NL);
    float4* p4 = (float4*)p;
    #pragma unroll
    for (int i = 0; i < 16; i++) p4[t + (i << 8)] = s4[t + (i << 8)];
    __syncthreads();

    int w = t >> 5, lane = t & 31;
    for (int rr = 0; rr < 4; rr++) {
        int r  = (w << 2) + rr;
        int qg = (qt << 5) + r;
        int nv = qg + 1;                       // valid prefix length
        float    ev[16];
        unsigned uv[16];
        float    svv[16];
        #pragma unroll
        for (int ii = 0; ii < 16; ii++) {
            int j = lane + (ii << 5);
            bool val = j < nv;
            float s = val ? p[(r << 9) + j] : NEGINF;
            svv[ii] = s;
            unsigned bits = __float_as_uint(s);
            uv[ii] = val ? ((bits & 0x80000000u) ? ~bits : (bits | 0x80000000u)) : 0u;
        }
        unsigned T = 1u;                       // nv<=256: keep every valid element
        if (nv > 256) {
            T = 0u;
            for (int bit = 31; bit >= 0; bit--) {
                unsigned cand = T | (1u << bit);
                int c = 0;
                #pragma unroll
                for (int ii = 0; ii < 16; ii++) c += (uv[ii] >= cand);
                c = __reduce_add_sync(0xffffffffu, c);
                if (c >= 256) T = cand;
            }
        }
        float m = NEGINF;
        #pragma unroll
        for (int ii = 0; ii < 16; ii++)
            if (uv[ii] >= T) m = fmaxf(m, svv[ii]);
        #pragma unroll
        for (int off = 16; off > 0; off >>= 1)
            m = fmaxf(m, __shfl_xor_sync(0xffffffffu, m, off));
        float z = 0.f;
        #pragma unroll
        for (int ii = 0; ii < 16; ii++) {
            float e = (uv[ii] >= T) ? __expf(svv[ii] - m) : 0.f;
            ev[ii] = e;
            z += e;
        }
        #pragma unroll
        for (int off = 16; off > 0; off >>= 1)
            z += __shfl_xor_sync(0xffffffffu, z, off);
        float inv = 1.f / z;
        #pragma unroll
        for (int ii = 0; ii < 16; ii++) {
            int j = lane + (ii << 5);
            p[(r << 9) + j] = ev[ii] * inv;
        }
    }
    __syncthreads();

    // P @ V
    float acc[8] = {};
    int d = t & 63, rb = t >> 6;
    for (int jt = 0; jt < 8; jt++) {
        const float4* v4 = (const float4*)(v + ((size_t)(b*NL + (jt << 6)))*ND + (h << 6));
        float4* vt4 = (float4*)vt;
        #pragma unroll
        for (int i = 0; i < 4; i++) {
            int lin = t + (i << 8);           // 0..1023 float4s
            int jr = lin >> 4, d4 = lin & 15;
            vt4[lin] = v4[(size_t)jr*128 + d4];
        }
        __syncthreads();
        #pragma unroll 2
        for (int j = 0; j < 64; j++) {
            float vv = vt[(j << 6) + d];
            int jj = (jt << 6) + j;
            #pragma unroll
            for (int i = 0; i < 8; i++)
                acc[i] += p[((rb + (i << 2)) << 9) + jj] * vv;
        }
        __syncthreads();
    }
    #pragma unroll
    for (int i = 0; i < 8; i++) {
        int row = (qt << 5) + rb + (i << 2);
        ao[((size_t)(b*NL + row))*ND + (h << 6) + d] = acc[i];
    }
}

// ---------------- launch ----------------
extern "C" void kernel_launch(void* const* d_in, const int* in_sizes, int n_in,
                              void* d_out, int out_size) {
    const float* x     = (const float*)d_in[0];
    const float* tf    = (const float*)d_in[1];
    const float* in_w  = (const float*)d_in[2];
    const float* in_b  = (const float*)d_in[3];
    const float* pe    = (const float*)d_in[4];
    const float* tw    = (const float*)d_in[5];
    const float* tb    = (const float*)d_in[6];
    const float* ps    = (const float*)d_in[7];
    const float* ts    = (const float*)d_in[8];
    const float* convw = (const float*)d_in[9];
    const float* convb = (const float*)d_in[10];
    const float* qw    = (const float*)d_in[11];
    const float* qb    = (const float*)d_in[12];
    const float* kw    = (const float*)d_in[13];
    const float* kb    = (const float*)d_in[14];
    const float* vw    = (const float*)d_in[15];
    const float* vb    = (const float*)d_in[16];
    const float* ow    = (const float*)d_in[17];
    const float* ob    = (const float*)d_in[18];
    const float* f1w   = (const float*)d_in[19];
    const float* f1b   = (const float*)d_in[20];
    const float* f2w   = (const float*)d_in[21];
    const float* f2b   = (const float*)d_in[22];
    const float* n1s   = (const float*)d_in[23];
    const float* n1b   = (const float*)d_in[24];
    const float* n2s   = (const float*)d_in[25];
    const float* n2b   = (const float*)d_in[26];

    float *h, *tbuf, *qv, *kv, *vv, *ao, *mid, *sc, *cw;
    cudaGetSymbolAddress((void**)&h,    g_h);
    cudaGetSymbolAddress((void**)&tbuf, g_t);
    cudaGetSymbolAddress((void**)&qv,   g_q);
    cudaGetSymbolAddress((void**)&kv,   g_k);
    cudaGetSymbolAddress((void**)&vv,   g_v);
    cudaGetSymbolAddress((void**)&ao,   g_ao);
    cudaGetSymbolAddress((void**)&mid,  g_mid);
    cudaGetSymbolAddress((void**)&sc,   g_sc);
    cudaGetSymbolAddress((void**)&cw,   g_cw);

    cudaFuncSetAttribute(attn_kernel, cudaFuncAttributeMaxDynamicSharedMemorySize, 81920);

    // conv weight re-layout (deterministic each call)
    tconv_kernel<<<(NE*3*ND*ND)/256, 256>>>(convw, cw);

    // input embedding
    embed_kernel<<<NBL, 256>>>(x, tf, in_w, in_b, pe, tw, tb, ps, ts, h);

    dim3 g512(ND/128, NBL/128);     // N=512  -> (4, 32)
    dim3 gqkv(ND/128, NBL/128, 3);  // merged QKV
    dim3 gdf (NDF/128, NBL/128);    // N=2048 -> (16, 32)

    for (int l = 0; l < NE; l++) {
        // causal conv (K = 3*512 = 1536) -> tbuf, then LN1 -> h
        gemm_kernel<1,0,0><<<g512, 256>>>(h, cw + (size_t)l*3*ND*ND, convb + l*ND,
                                          nullptr, tbuf, ND, 3*ND);
        ln_kernel<<<NBL, 256>>>(h, tbuf, n1s + l*ND, n1b + l*ND, h);

        // Q, K, V projections (one merged launch)
        gemm_qkv_kernel<<<gqkv, 256>>>(h,
            qw + (size_t)l*ND*ND, kw + (size_t)l*ND*ND, vw + (size_t)l*ND*ND,
            qb + l*ND, kb + l*ND, vb + l*ND,
            qv, kv, vv);

        // scores (lower-triangular tiles only)
        scores_kernel<<<dim3(8, 8, 64), 256>>>(qv, kv, sc);

        // top-k select + softmax + P@V
        attn_kernel<<<dim3(16, 64), 256, 81920>>>(sc, vv, ao);

        // output projection -> tbuf, LN2 -> h
        gemm_kernel<0,0,0><<<g512, 256>>>(ao, ow + (size_t)l*ND*ND, ob + l*ND, nullptr, tbuf, ND, ND);
        ln_kernel<<<NBL, 256>>>(h, tbuf, n2s + l*ND, n2b + l*ND, h);

        // FFN
        gemm_kernel<0,1,0><<<gdf, 256>>>(h, f1w + (size_t)l*ND*NDF, f1b + l*NDF,
                                         nullptr, mid, NDF, ND);
        float* outp = (l == NE-1) ? (float*)d_out : h;
        gemm_kernel<0,0,1><<<g512, 256>>>(mid, f2w + (size_t)l*NDF*ND, f2b + l*ND,
                                          h, outp, ND, NDF);
    }
}

// round 9
// speedup vs baseline: 1.9857x; 1.9857x over previous
#include <cuda_runtime.h>
#include <cuda_bf16.h>
#include <cstdint>
#include <cstddef>

#define NB 8
#define NL 512
#define ND 512
#define NH 8
#define HD 64
#define NE 4
#define NDF 2048
#define NBL 4096   // NB*NL

#define NEGINF __int_as_float(0xff800000)

// per-layer weight block (bf16, [N][K] layouts)
#define LSTRIDE 3932160
#define W_CONV 0               // [512][1536]
#define W_Q    786432          // [512][512]
#define W_K    1048576
#define W_V    1310720
#define W_O    1572864
#define W_F1   1835008         // [2048][512]
#define W_F2   2883584         // [512][2048]

// smem (bytes): padded rows of 72 bf16 = 144 B (conflict-free ldmatrix)
#define SM_AHI  0
#define SM_ALO  18432          // 128*144
#define SM_BHI  36864
#define SM_BLO  46080          // + 64*144
#define SM_SZ   55296

// ---------------- scratch (static device allocations) ----------------
__device__ float g_h [NBL*ND];
__device__ float g_t [NBL*ND];
__device__ float g_q [NBL*ND];
__device__ float g_k [NBL*ND];
__device__ float g_v [NBL*ND];
__device__ float g_sc[(size_t)64*NL*NL];     // [B*H][L][L]
__device__ __nv_bfloat16 g_whi[(size_t)NE*LSTRIDE];
__device__ __nv_bfloat16 g_wlo[(size_t)NE*LSTRIDE];
__device__ __nv_bfloat16 g_hhi[NBL*ND],  g_hlo[NBL*ND];
__device__ __nv_bfloat16 g_aohi[NBL*ND], g_aolo[NBL*ND];
__device__ __nv_bfloat16 g_mhi[NBL*NDF], g_mlo[NBL*NDF];

// ---------------- helpers ----------------
__device__ __forceinline__ uint32_t smem_u32(const void* p) {
    uint32_t a;
    asm("{ .reg .u64 t; cvta.to.shared.u64 t, %1; cvt.u32.u64 %0, t; }" : "=r"(a) : "l"(p));
    return a;
}
__device__ __forceinline__ void ldsm4(uint32_t* r, uint32_t addr) {
    asm volatile("ldmatrix.sync.aligned.m8n8.x4.shared.b16 {%0,%1,%2,%3}, [%4];"
                 : "=r"(r[0]), "=r"(r[1]), "=r"(r[2]), "=r"(r[3]) : "r"(addr));
}
__device__ __forceinline__ void mma16816(float* c, const uint32_t* a, const uint32_t* b) {
    asm volatile(
        "mma.sync.aligned.m16n8k16.row.col.f32.bf16.bf16.f32 "
        "{%0,%1,%2,%3}, {%4,%5,%6,%7}, {%8,%9}, {%0,%1,%2,%3};"
        : "+f"(c[0]), "+f"(c[1]), "+f"(c[2]), "+f"(c[3])
        : "r"(a[0]), "r"(a[1]), "r"(a[2]), "r"(a[3]), "r"(b[0]), "r"(b[1]));
}
__device__ __forceinline__ void split2(float x, __nv_bfloat16& hi, __nv_bfloat16& lo) {
    hi = __float2bfloat16(x);
    lo = __float2bfloat16(x - __bfloat162float(hi));
}

// ---------------- weight prep: transpose+split [K][N] -> [N][K] bf16 hi/lo -------------
__global__ __launch_bounds__(256) void tsplit_kernel(
    const float* __restrict__ src, __nv_bfloat16* __restrict__ hi,
    __nv_bfloat16* __restrict__ lo, int K, int N,
    size_t src_stride, size_t dst_stride)
{
    __shared__ float tile[32][33];
    int kb = blockIdx.y << 5, nb = blockIdx.x << 5;
    const float* s = src + (size_t)blockIdx.z * src_stride;
    int tx = threadIdx.x, ty = threadIdx.y;   // 32 x 8
    #pragma unroll
    for (int j = 0; j < 4; j++)
        tile[ty + j*8][tx] = s[(size_t)(kb + ty + j*8)*N + nb + tx];
    __syncthreads();
    size_t dbase = (size_t)blockIdx.z * dst_stride;
    #pragma unroll
    for (int j = 0; j < 4; j++) {
        float v = tile[tx][ty + j*8];
        __nv_bfloat16 h_, l_; split2(v, h_, l_);
        size_t o = dbase + (size_t)(nb + ty + j*8)*K + kb + tx;
        hi[o] = h_; lo[o] = l_;
    }
}

// conv weights: w[l][o][i][tap] -> dst[l-block][o][tap*512+i] bf16 hi/lo
__global__ __launch_bounds__(256) void convprep_kernel(
    const float* __restrict__ w, __nv_bfloat16* __restrict__ hi, __nv_bfloat16* __restrict__ lo)
{
    int idx = blockIdx.x * 256 + threadIdx.x;   // 4*512*1536
    int l = idx / (512*1536);
    int r = idx % (512*1536);
    int o = r / 1536;
    int k = r % 1536;
    int tap = k >> 9, i = k & 511;
    float v = w[(((size_t)l*512 + o)*512 + i)*3 + tap];
    __nv_bfloat16 h_, l_; split2(v, h_, l_);
    size_t dst = (size_t)l*LSTRIDE + (size_t)o*1536 + k;
    hi[dst] = h_; lo[dst] = l_;
}

// ---------------- input embedding (also emits bf16 split) ----------------
__global__ __launch_bounds__(256) void embed_kernel(
    const float* __restrict__ x, const float* __restrict__ tf,
    const float* __restrict__ inw, const float* __restrict__ inb,
    const float* __restrict__ pe, const float* __restrict__ tw,
    const float* __restrict__ tb, const float* __restrict__ ps,
    const float* __restrict__ ts, float* __restrict__ out,
    __nv_bfloat16* __restrict__ ohi, __nv_bfloat16* __restrict__ olo)
{
    int bl = blockIdx.x;
    int t  = threadIdx.x;
    __shared__ float xs[64];
    __shared__ float t2[2];
    if (t < 64) xs[t] = x[bl*64 + t];
    if (t < 2)  t2[t] = tf[bl*2 + t];
    __syncthreads();
    float pss = ps[0], tss = ts[0];
    int pos = bl & (NL-1);
    #pragma unroll
    for (int rep = 0; rep < 2; rep++) {
        int d = t + (rep << 8);
        float acc = inb[d];
        #pragma unroll 16
        for (int i = 0; i < 64; i++) acc += xs[i] * inw[i*ND + d];
        acc += pss * pe[pos*ND + d];
        acc += tss * (t2[0]*tw[d] + t2[1]*tw[ND + d] + tb[d]);
        out[bl*ND + d] = acc;
        __nv_bfloat16 h_, l_; split2(acc, h_, l_);
        ohi[bl*ND + d] = h_; olo[bl*ND + d] = l_;
    }
}

// ---------------- HMMA GEMM: 128x64 tile, K-chunks of 64, bf16 3-way split -----------
// 256 threads, 8 warps: wm = wid&3 (32 M-rows), wn = wid>>2 (32 N-cols).
template<int CONV, int RELU, int ADDRES, int OUTF32, int OUTSPLIT>
__device__ __forceinline__ void tgemm_body(
    const __nv_bfloat16* __restrict__ Ahi, const __nv_bfloat16* __restrict__ Alo,
    const __nv_bfloat16* __restrict__ Bhi, const __nv_bfloat16* __restrict__ Blo,
    const float* __restrict__ bias, const float* __restrict__ res,
    float* __restrict__ C, __nv_bfloat16* __restrict__ Chi, __nv_bfloat16* __restrict__ Clo,
    int N, int K, int bn, int bm)
{
    extern __shared__ char smem[];
    uint32_t sb = smem_u32(smem);
    int t = threadIdx.x;
    int lane = t & 31, wid = t >> 5;
    int wm = wid & 3, wn = wid >> 2;

    // ldmatrix per-lane address pieces
    int sub = lane >> 3, r8 = lane & 7;
    uint32_t aOff = (uint32_t)(wm*32 + (sub & 1)*8 + r8) * 144 + (uint32_t)(sub >> 1) * 16;
    uint32_t bOff = (uint32_t)(wn*32 + (sub >> 1)*8 + r8) * 144 + (uint32_t)(sub & 1) * 16;

    float acc[2][4][4];
    #pragma unroll
    for (int i = 0; i < 2; i++)
        #pragma unroll
        for (int j = 0; j < 4; j++)
            #pragma unroll
            for (int q = 0; q < 4; q++) acc[i][j][q] = 0.f;

    int nk = K >> 6;
    for (int c = 0; c < nk; c++) {
        int k0 = c << 6;
        // ---- A tile: 128 rows x 64 bf16; thread loads half a row (32 bf16) ----
        {
            int row = t >> 1, half = t & 1;
            int m = bm + row;
            const uint4* srh; const uint4* srl;
            bool zero = false;
            if (CONV) {
                int tap = k0 >> 9;
                int i0  = (k0 & 511) + half*32;
                zero = ((m & 511) + tap - 2) < 0;
                int rr = m + tap - 2;
                srh = (const uint4*)&Ahi[(size_t)rr*512 + i0];
                srl = (const uint4*)&Alo[(size_t)rr*512 + i0];
            } else {
                srh = (const uint4*)&Ahi[(size_t)m*K + k0 + half*32];
                srl = (const uint4*)&Alo[(size_t)m*K + k0 + half*32];
            }
            uint32_t so = (uint32_t)row*144 + (uint32_t)half*64;
            #pragma unroll
            for (int u = 0; u < 4; u++) {
                uint4 vh, vl;
                if (zero) { vh = make_uint4(0,0,0,0); vl = vh; }
                else      { vh = srh[u]; vl = srl[u]; }
                *(uint4*)(smem + SM_AHI + so + u*16) = vh;
                *(uint4*)(smem + SM_ALO + so + u*16) = vl;
            }
        }
        // ---- B tile: 64 rows x 64 bf16; thread loads quarter row (16 bf16) ----
        {
            int row = t >> 2, q = t & 3;
            const uint4* sh = (const uint4*)&Bhi[(size_t)(bn + row)*K + k0 + q*16];
            const uint4* sl = (const uint4*)&Blo[(size_t)(bn + row)*K + k0 + q*16];
            uint32_t so = (uint32_t)row*144 + (uint32_t)q*32;
            #pragma unroll
            for (int u = 0; u < 2; u++) {
                *(uint4*)(smem + SM_BHI + so + u*16) = sh[u];
                *(uint4*)(smem + SM_BLO + so + u*16) = sl[u];
            }
        }
        __syncthreads();

        #pragma unroll
        for (int ks = 0; ks < 4; ks++) {
            uint32_t ko = ks*32;
            uint32_t ah0[4], ah1[4], al0[4], al1[4];
            uint32_t bh0[4], bh1[4], bl0[4], bl1[4];
            ldsm4(ah0, sb + SM_AHI + aOff + ko);
            ldsm4(ah1, sb + SM_AHI + aOff + 16*144 + ko);
            ldsm4(al0, sb + SM_ALO + aOff + ko);
            ldsm4(al1, sb + SM_ALO + aOff + 16*144 + ko);
            ldsm4(bh0, sb + SM_BHI + bOff + ko);
            ldsm4(bh1, sb + SM_BHI + bOff + 16*144 + ko);
            ldsm4(bl0, sb + SM_BLO + bOff + ko);
            ldsm4(bl1, sb + SM_BLO + bOff + 16*144 + ko);
            #pragma unroll
            for (int mt = 0; mt < 2; mt++) {
                const uint32_t* ah = mt ? ah1 : ah0;
                const uint32_t* al = mt ? al1 : al0;
                #pragma unroll
                for (int nt = 0; nt < 4; nt++) {
                    const uint32_t* bh = ((nt < 2) ? bh0 : bh1) + (nt & 1)*2;
                    const uint32_t* bl = ((nt < 2) ? bl0 : bl1) + (nt & 1)*2;
                    mma16816(acc[mt][nt], ah, bh);
                    mma16816(acc[mt][nt], ah, bl);
                    mma16816(acc[mt][nt], al, bh);
                }
            }
        }
        __syncthreads();
    }

    // ---- epilogue ----
    int g = lane >> 2, tc = lane & 3;
    #pragma unroll
    for (int mt = 0; mt < 2; mt++) {
        #pragma unroll
        for (int h2 = 0; h2 < 2; h2++) {
            int row = bm + wm*32 + mt*16 + h2*8 + g;
            #pragma unroll
            for (int nt = 0; nt < 4; nt++) {
                int col = bn + wn*32 + nt*8 + tc*2;
                float v0 = acc[mt][nt][h2*2+0] + bias[col];
                float v1 = acc[mt][nt][h2*2+1] + bias[col+1];
                if (RELU) { v0 = fmaxf(v0, 0.f); v1 = fmaxf(v1, 0.f); }
                if (ADDRES) {
                    float2 r2 = *(const float2*)&res[(size_t)row*N + col];
                    v0 += r2.x; v1 += r2.y;
                }
                if (OUTF32) {
                    float2 o; o.x = v0; o.y = v1;
                    *(float2*)&C[(size_t)row*N + col] = o;
                }
                if (OUTSPLIT) {
                    __nv_bfloat16 h0, l0, h1, l1;
                    split2(v0, h0, l0);
                    split2(v1, h1, l1);
                    __nv_bfloat162 hp; hp.x = h0; hp.y = h1;
                    __nv_bfloat162 lp; lp.x = l0; lp.y = l1;
                    *(__nv_bfloat162*)&Chi[(size_t)row*N + col] = hp;
                    *(__nv_bfloat162*)&Clo[(size_t)row*N + col] = lp;
                }
            }
        }
    }
}

template<int CONV, int RELU, int ADDRES, int OUTF32, int OUTSPLIT>
__global__ __launch_bounds__(256) void tgemm_kernel(
    const __nv_bfloat16* __restrict__ Ahi, const __nv_bfloat16* __restrict__ Alo,
    const __nv_bfloat16* __restrict__ Bhi, const __nv_bfloat16* __restrict__ Blo,
    const float* __restrict__ bias, const float* __restrict__ res,
    float* __restrict__ C, __nv_bfloat16* __restrict__ Chi, __nv_bfloat16* __restrict__ Clo,
    int N, int K)
{
    tgemm_body<CONV, RELU, ADDRES, OUTF32, OUTSPLIT>(
        Ahi, Alo, Bhi, Blo, bias, res, C, Chi, Clo, N, K,
        blockIdx.x << 6, blockIdx.y << 7);
}

// merged Q/K/V: blockIdx.z selects weights (contiguous blocks), bias, output
__global__ __launch_bounds__(256) void tgemm_qkv_kernel(
    const __nv_bfloat16* __restrict__ Ahi, const __nv_bfloat16* __restrict__ Alo,
    const __nv_bfloat16* __restrict__ Whi, const __nv_bfloat16* __restrict__ Wlo,
    const float* __restrict__ b0, const float* __restrict__ b1, const float* __restrict__ b2,
    float* __restrict__ c0, float* __restrict__ c1, float* __restrict__ c2)
{
    int z = blockIdx.z;
    const __nv_bfloat16* bh = Whi + (size_t)z * 262144;
    const __nv_bfloat16* bl = Wlo + (size_t)z * 262144;
    const float* bia = (z == 0) ? b0 : (z == 1) ? b1 : b2;
    float*       c   = (z == 0) ? c0 : (z == 1) ? c1 : c2;
    tgemm_body<0, 0, 0, 1, 0>(Ahi, Alo, bh, bl, bia, nullptr, c, nullptr, nullptr,
                              ND, ND, blockIdx.x << 6, blockIdx.y << 7);
}

// ---------------- fused add + LayerNorm (emits fp32 + bf16 split) ----------------
__global__ __launch_bounds__(256) void ln_kernel(
    const float* __restrict__ a, const float* __restrict__ b,
    const float* __restrict__ sc, const float* __restrict__ bi,
    float* __restrict__ out, __nv_bfloat16* __restrict__ ohi, __nv_bfloat16* __restrict__ olo)
{
    int row = blockIdx.x;
    int t = threadIdx.x;
    const float* ar = a + (size_t)row*ND;
    const float* br = b + (size_t)row*ND;
    float v0 = ar[t]       + br[t];
    float v1 = ar[t + 256] + br[t + 256];
    float s1 = v0 + v1;
    float s2 = v0*v0 + v1*v1;
    #pragma unroll
    for (int off = 16; off > 0; off >>= 1) {
        s1 += __shfl_xor_sync(0xffffffffu, s1, off);
        s2 += __shfl_xor_sync(0xffffffffu, s2, off);
    }
    __shared__ float r1[8], r2[8], mv[2];
    int w = t >> 5, lane = t & 31;
    if (lane == 0) { r1[w] = s1; r2[w] = s2; }
    __syncthreads();
    if (t == 0) {
        float a1 = 0.f, a2 = 0.f;
        #pragma unroll
        for (int i = 0; i < 8; i++) { a1 += r1[i]; a2 += r2[i]; }
        float mean = a1 * (1.f/512.f);
        float var  = a2 * (1.f/512.f) - mean*mean;
        mv[0] = mean;
        mv[1] = rsqrtf(var + 1e-5f);
    }
    __syncthreads();
    float mean = mv[0], rstd = mv[1];
    float o0 = (v0 - mean)*rstd*sc[t]       + bi[t];
    float o1 = (v1 - mean)*rstd*sc[t + 256] + bi[t + 256];
    out[(size_t)row*ND + t]       = o0;
    out[(size_t)row*ND + t + 256] = o1;
    __nv_bfloat16 h_, l_;
    split2(o0, h_, l_);
    ohi[(size_t)row*ND + t] = h_;       olo[(size_t)row*ND + t] = l_;
    split2(o1, h_, l_);
    ohi[(size_t)row*ND + t + 256] = h_; olo[(size_t)row*ND + t + 256] = l_;
}

// ---------------- scores: per (b,h), lower-triangular 64x64 tiles of q @ k^T * scale ----
__global__ __launch_bounds__(256) void scores_kernel(
    const float* __restrict__ q, const float* __restrict__ k, float* __restrict__ sc)
{
    int nt = blockIdx.x, mt = blockIdx.y, bh = blockIdx.z;
    if (nt > mt) return;
    int b = bh >> 3, h = bh & 7;
    __shared__ float Qs[64*65];
    __shared__ float Ks[64*65];
    int t = threadIdx.x;
    const float* qb = q + ((size_t)(b*NL + mt*64))*ND + h*HD;
    const float* kb = k + ((size_t)(b*NL + nt*64))*ND + h*HD;
    #pragma unroll
    for (int i = 0; i < 16; i++) {
        int lin = t + (i << 8);
        int r = lin >> 6, d = lin & 63;
        Qs[r*65 + d] = qb[(size_t)r*ND + d];
        Ks[r*65 + d] = kb[(size_t)r*ND + d];
    }
    __syncthreads();
    int tx = t & 15, ty = t >> 4;
    float acc[4][4] = {};
    #pragma unroll 4
    for (int d = 0; d < 64; d++) {
        float ar[4], br[4];
        #pragma unroll
        for (int i = 0; i < 4; i++) ar[i] = Qs[((ty<<2)+i)*65 + d];
        #pragma unroll
        for (int j = 0; j < 4; j++) br[j] = Ks[((tx<<2)+j)*65 + d];
        #pragma unroll
        for (int i = 0; i < 4; i++)
            #pragma unroll
            for (int j = 0; j < 4; j++)
                acc[i][j] += ar[i]*br[j];
    }
    float* base = sc + (size_t)bh*NL*NL;
    #pragma unroll
    for (int i = 0; i < 4; i++) {
        int m = mt*64 + (ty<<2) + i;
        float4 o;
        o.x = acc[i][0]*0.125f; o.y = acc[i][1]*0.125f;
        o.z = acc[i][2]*0.125f; o.w = acc[i][3]*0.125f;
        *(float4*)&base[(size_t)m*NL + nt*64 + (tx<<2)] = o;
    }
}

// ---------------- top-k(256) select + softmax + P@V (emits ao bf16 split) -----------
__global__ __launch_bounds__(256) void attn_kernel(
    const float* __restrict__ sc, const float* __restrict__ v,
    __nv_bfloat16* __restrict__ aohi, __nv_bfloat16* __restrict__ aolo)
{
    extern __shared__ float sm[];
    float* p  = sm;             // 32*512
    float* vt = sm + 32*512;    // 64*64
    int qt = blockIdx.x, bh = blockIdx.y;
    int b = bh >> 3, h = bh & 7;
    int t = threadIdx.x;

    const float4* s4 = (const float4*)(sc + (size_t)bh*NL*NL + (size_t)(qt*32)*NL);
    float4* p4 = (float4*)p;
    #pragma unroll
    for (int i = 0; i < 16; i++) p4[t + (i << 8)] = s4[t + (i << 8)];
    __syncthreads();

    int w = t >> 5, lane = t & 31;
    for (int rr = 0; rr < 4; rr++) {
        int r  = (w << 2) + rr;
        int qg = (qt << 5) + r;
        int nv = qg + 1;
        float    ev[16];
        unsigned uv[16];
        float    svv[16];
        #pragma unroll
        for (int ii = 0; ii < 16; ii++) {
            int j = lane + (ii << 5);
            bool val = j < nv;
            float s = val ? p[(r << 9) + j] : NEGINF;
            svv[ii] = s;
            unsigned bits = __float_as_uint(s);
            uv[ii] = val ? ((bits & 0x80000000u) ? ~bits : (bits | 0x80000000u)) : 0u;
        }
        unsigned T = 1u;
        if (nv > 256) {
            T = 0u;
            for (int bit = 31; bit >= 0; bit--) {
                unsigned cand = T | (1u << bit);
                int c = 0;
                #pragma unroll
                for (int ii = 0; ii < 16; ii++) c += (uv[ii] >= cand);
                c = __reduce_add_sync(0xffffffffu, c);
                if (c >= 256) T = cand;
            }
        }
        float m = NEGINF;
        #pragma unroll
        for (int ii = 0; ii < 16; ii++)
            if (uv[ii] >= T) m = fmaxf(m, svv[ii]);
        #pragma unroll
        for (int off = 16; off > 0; off >>= 1)
            m = fmaxf(m, __shfl_xor_sync(0xffffffffu, m, off));
        float z = 0.f;
        #pragma unroll
        for (int ii = 0; ii < 16; ii++) {
            float e = (uv[ii] >= T) ? __expf(svv[ii] - m) : 0.f;
            ev[ii] = e;
            z += e;
        }
        #pragma unroll
        for (int off = 16; off > 0; off >>= 1)
            z += __shfl_xor_sync(0xffffffffu, z, off);
        float inv = 1.f / z;
        #pragma unroll
        for (int ii = 0; ii < 16; ii++) {
            int j = lane + (ii << 5);
            p[(r << 9) + j] = ev[ii] * inv;
        }
    }
    __syncthreads();

    float acc[8] = {};
    int d = t & 63, rb = t >> 6;
    for (int jt = 0; jt < 8; jt++) {
        const float4* v4 = (const float4*)(v + ((size_t)(b*NL + (jt << 6)))*ND + (h << 6));
        float4* vt4 = (float4*)vt;
        #pragma unroll
        for (int i = 0; i < 4; i++) {
            int lin = t + (i << 8);
            int jr = lin >> 4, d4 = lin & 15;
            vt4[lin] = v4[(size_t)jr*128 + d4];
        }
        __syncthreads();
        #pragma unroll 2
        for (int j = 0; j < 64; j++) {
            float vv = vt[(j << 6) + d];
            int jj = (jt << 6) + j;
            #pragma unroll
            for (int i = 0; i < 8; i++)
                acc[i] += p[((rb + (i << 2)) << 9) + jj] * vv;
        }
        __syncthreads();
    }
    #pragma unroll
    for (int i = 0; i < 8; i++) {
        int row = (qt << 5) + rb + (i << 2);
        size_t idx = ((size_t)(b*NL + row))*ND + (h << 6) + d;
        __nv_bfloat16 h_, l_;
        split2(acc[i], h_, l_);
        aohi[idx] = h_; aolo[idx] = l_;
    }
}

// ---------------- launch ----------------
extern "C" void kernel_launch(void* const* d_in, const int* in_sizes, int n_in,
                              void* d_out, int out_size) {
    const float* x     = (const float*)d_in[0];
    const float* tf    = (const float*)d_in[1];
    const float* in_w  = (const float*)d_in[2];
    const float* in_b  = (const float*)d_in[3];
    const float* pe    = (const float*)d_in[4];
    const float* tw    = (const float*)d_in[5];
    const float* tb    = (const float*)d_in[6];
    const float* ps    = (const float*)d_in[7];
    const float* ts    = (const float*)d_in[8];
    const float* convw = (const float*)d_in[9];
    const float* convb = (const float*)d_in[10];
    const float* qw    = (const float*)d_in[11];
    const float* qb    = (const float*)d_in[12];
    const float* kw    = (const float*)d_in[13];
    const float* kb    = (const float*)d_in[14];
    const float* vw    = (const float*)d_in[15];
    const float* vb    = (const float*)d_in[16];
    const float* ow    = (const float*)d_in[17];
    const float* ob    = (const float*)d_in[18];
    const float* f1w   = (const float*)d_in[19];
    const float* f1b   = (const float*)d_in[20];
    const float* f2w   = (const float*)d_in[21];
    const float* f2b   = (const float*)d_in[22];
    const float* n1s   = (const float*)d_in[23];
    const float* n1b   = (const float*)d_in[24];
    const float* n2s   = (const float*)d_in[25];
    const float* n2b   = (const float*)d_in[26];

    float *h, *tbuf, *qv, *kv, *vv, *scb;
    __nv_bfloat16 *whi, *wlo, *hhi, *hlo, *aohi, *aolo, *mhi, *mlo;
    cudaGetSymbolAddress((void**)&h,    g_h);
    cudaGetSymbolAddress((void**)&tbuf, g_t);
    cudaGetSymbolAddress((void**)&qv,   g_q);
    cudaGetSymbolAddress((void**)&kv,   g_k);
    cudaGetSymbolAddress((void**)&vv,   g_v);
    cudaGetSymbolAddress((void**)&scb,  g_sc);
    cudaGetSymbolAddress((void**)&whi,  g_whi);
    cudaGetSymbolAddress((void**)&wlo,  g_wlo);
    cudaGetSymbolAddress((void**)&hhi,  g_hhi);
    cudaGetSymbolAddress((void**)&hlo,  g_hlo);
    cudaGetSymbolAddress((void**)&aohi, g_aohi);
    cudaGetSymbolAddress((void**)&aolo, g_aolo);
    cudaGetSymbolAddress((void**)&mhi,  g_mhi);
    cudaGetSymbolAddress((void**)&mlo,  g_mlo);

    cudaFuncSetAttribute(attn_kernel, cudaFuncAttributeMaxDynamicSharedMemorySize, 81920);
    cudaFuncSetAttribute(tgemm_kernel<1,0,0,1,0>, cudaFuncAttributeMaxDynamicSharedMemorySize, SM_SZ);
    cudaFuncSetAttribute(tgemm_kernel<0,0,0,1,0>, cudaFuncAttributeMaxDynamicSharedMemorySize, SM_SZ);
    cudaFuncSetAttribute(tgemm_kernel<0,1,0,0,1>, cudaFuncAttributeMaxDynamicSharedMemorySize, SM_SZ);
    cudaFuncSetAttribute(tgemm_kernel<0,0,1,1,1>, cudaFuncAttributeMaxDynamicSharedMemorySize, SM_SZ);
    cudaFuncSetAttribute(tgemm_kernel<0,0,1,1,0>, cudaFuncAttributeMaxDynamicSharedMemorySize, SM_SZ);
    cudaFuncSetAttribute(tgemm_qkv_kernel, cudaFuncAttributeMaxDynamicSharedMemorySize, SM_SZ);

    // ---- weight prep (bf16 split, [N][K]) ----
    convprep_kernel<<<(NE*512*1536)/256, 256>>>(convw, whi, wlo);
    dim3 tb32(32, 8);
    tsplit_kernel<<<dim3(16, 16, 4), tb32>>>(qw,  whi + W_Q,  wlo + W_Q,  512,  512,  262144,  LSTRIDE);
    tsplit_kernel<<<dim3(16, 16, 4), tb32>>>(kw,  whi + W_K,  wlo + W_K,  512,  512,  262144,  LSTRIDE);
    tsplit_kernel<<<dim3(16, 16, 4), tb32>>>(vw,  whi + W_V,  wlo + W_V,  512,  512,  262144,  LSTRIDE);
    tsplit_kernel<<<dim3(16, 16, 4), tb32>>>(ow,  whi + W_O,  wlo + W_O,  512,  512,  262144,  LSTRIDE);
    tsplit_kernel<<<dim3(64, 16, 4), tb32>>>(f1w, whi + W_F1, wlo + W_F1, 512,  2048, 1048576, LSTRIDE);
    tsplit_kernel<<<dim3(16, 64, 4), tb32>>>(f2w, whi + W_F2, wlo + W_F2, 2048, 512,  1048576, LSTRIDE);

    // ---- input embedding ----
    embed_kernel<<<NBL, 256>>>(x, tf, in_w, in_b, pe, tw, tb, ps, ts, h, hhi, hlo);

    dim3 g512(8, 32);         // N=512 tiles
    dim3 gqkv(8, 32, 3);
    dim3 gdf (32, 32);        // N=2048 tiles

    for (int l = 0; l < NE; l++) {
        const __nv_bfloat16* lwh = whi + (size_t)l*LSTRIDE;
        const __nv_bfloat16* lwl = wlo + (size_t)l*LSTRIDE;

        // causal conv (K=1536) -> tbuf fp32, then LN1 -> h (+split)
        tgemm_kernel<1,0,0,1,0><<<g512, 256, SM_SZ>>>(
            hhi, hlo, lwh + W_CONV, lwl + W_CONV, convb + l*ND,
            nullptr, tbuf, nullptr, nullptr, ND, 3*ND);
        ln_kernel<<<NBL, 256>>>(h, tbuf, n1s + l*ND, n1b + l*ND, h, hhi, hlo);

        // Q, K, V projections (merged)
        tgemm_qkv_kernel<<<gqkv, 256, SM_SZ>>>(
            hhi, hlo, lwh + W_Q, lwl + W_Q,
            qb + l*ND, kb + l*ND, vb + l*ND, qv, kv, vv);

        // scores (lower-triangular tiles only)
        scores_kernel<<<dim3(8, 8, 64), 256>>>(qv, kv, scb);

        // top-k select + softmax + P@V -> ao split
        attn_kernel<<<dim3(16, 64), 256, 81920>>>(scb, vv, aohi, aolo);

        // output projection -> tbuf fp32, LN2 -> h (+split)
        tgemm_kernel<0,0,0,1,0><<<g512, 256, SM_SZ>>>(
            aohi, aolo, lwh + W_O, lwl + W_O, ob + l*ND,
            nullptr, tbuf, nullptr, nullptr, ND, ND);
        ln_kernel<<<NBL, 256>>>(h, tbuf, n2s + l*ND, n2b + l*ND, h, hhi, hlo);

        // FFN1: relu, split-only out
        tgemm_kernel<0,1,0,0,1><<<gdf, 256, SM_SZ>>>(
            hhi, hlo, lwh + W_F1, lwl + W_F1, f1b + l*NDF,
            nullptr, nullptr, mhi, mlo, NDF, ND);

        // FFN2: +residual h; fp32 out (+split for next layer's conv)
        if (l < NE-1) {
            tgemm_kernel<0,0,1,1,1><<<g512, 256, SM_SZ>>>(
                mhi, mlo, lwh + W_F2, lwl + W_F2, f2b + l*ND,
                h, h, hhi, hlo, ND, NDF);
        } else {
            tgemm_kernel<0,0,1,1,0><<<g512, 256, SM_SZ>>>(
                mhi, mlo, lwh + W_F2, lwl + W_F2, f2b + l*ND,
                h, (float*)d_out, nullptr, nullptr, ND, NDF);
        }
    }
}

// round 11
// speedup vs baseline: 2.0547x; 1.0347x over previous
#include <cuda_runtime.h>
#include <cuda_bf16.h>
#include <cstdint>
#include <cstddef>

#define NB 8
#define NL 512
#define ND 512
#define NH 8
#define HD 64
#define NE 4
#define NDF 2048
#define NBL 4096   // NB*NL

#define NEGINF __int_as_float(0xff800000)

// per-layer weight block (bf16, [N][K] layouts)
#define LSTRIDE 3932160
#define W_CONV 0               // [512][1536]
#define W_Q    786432          // [512][512]
#define W_K    1048576
#define W_V    1310720
#define W_O    1572864
#define W_F1   1835008         // [2048][512]
#define W_F2   2883584         // [512][2048]

// smem (bytes): padded rows of 72 bf16 = 144 B (conflict-free ldmatrix)
#define SM_AHI  0
#define SM_ALO  18432          // 128*144
#define SM_BHI  36864
#define SM_BLO  46080          // + 64*144
#define SM_SZ   55296

// ---------------- scratch (static device allocations) ----------------
__device__ float g_h [NBL*ND];
__device__ float g_t [NBL*ND];
__device__ float g_v [NBL*ND];
__device__ float g_sc[(size_t)64*NL*NL];     // [B*H][L][L]
__device__ __nv_bfloat16 g_whi[(size_t)NE*LSTRIDE];
__device__ __nv_bfloat16 g_wlo[(size_t)NE*LSTRIDE];
__device__ __nv_bfloat16 g_hhi[NBL*ND],  g_hlo[NBL*ND];
__device__ __nv_bfloat16 g_qhi[NBL*ND],  g_qlo[NBL*ND];
__device__ __nv_bfloat16 g_khi[NBL*ND],  g_klo[NBL*ND];
__device__ __nv_bfloat16 g_aohi[NBL*ND], g_aolo[NBL*ND];
__device__ __nv_bfloat16 g_mhi[NBL*NDF], g_mlo[NBL*NDF];

// ---------------- helpers ----------------
__device__ __forceinline__ uint32_t smem_u32(const void* p) {
    uint32_t a;
    asm("{ .reg .u64 t; cvta.to.shared.u64 t, %1; cvt.u32.u64 %0, t; }" : "=r"(a) : "l"(p));
    return a;
}
__device__ __forceinline__ void ldsm4(uint32_t* r, uint32_t addr) {
    asm volatile("ldmatrix.sync.aligned.m8n8.x4.shared.b16 {%0,%1,%2,%3}, [%4];"
                 : "=r"(r[0]), "=r"(r[1]), "=r"(r[2]), "=r"(r[3]) : "r"(addr));
}
__device__ __forceinline__ void mma16816(float* c, const uint32_t* a, const uint32_t* b) {
    asm volatile(
        "mma.sync.aligned.m16n8k16.row.col.f32.bf16.bf16.f32 "
        "{%0,%1,%2,%3}, {%4,%5,%6,%7}, {%8,%9}, {%0,%1,%2,%3};"
        : "+f"(c[0]), "+f"(c[1]), "+f"(c[2]), "+f"(c[3])
        : "r"(a[0]), "r"(a[1]), "r"(a[2]), "r"(a[3]), "r"(b[0]), "r"(b[1]));
}
__device__ __forceinline__ void split2(float x, __nv_bfloat16& hi, __nv_bfloat16& lo) {
    hi = __float2bfloat16(x);
    lo = __float2bfloat16(x - __bfloat162float(hi));
}

// ---------------- weight prep: transpose+split [K][N] -> [N][K] bf16 hi/lo -------------
__global__ __launch_bounds__(256) void tsplit_kernel(
    const float* __restrict__ src, __nv_bfloat16* __restrict__ hi,
    __nv_bfloat16* __restrict__ lo, int K, int N,
    size_t src_stride, size_t dst_stride)
{
    __shared__ float tile[32][33];
    int kb = blockIdx.y << 5, nb = blockIdx.x << 5;
    const float* s = src + (size_t)blockIdx.z * src_stride;
    int tx = threadIdx.x, ty = threadIdx.y;   // 32 x 8
    #pragma unroll
    for (int j = 0; j < 4; j++)
        tile[ty + j*8][tx] = s[(size_t)(kb + ty + j*8)*N + nb + tx];
    __syncthreads();
    size_t dbase = (size_t)blockIdx.z * dst_stride;
    #pragma unroll
    for (int j = 0; j < 4; j++) {
        float v = tile[tx][ty + j*8];
        __nv_bfloat16 h_, l_; split2(v, h_, l_);
        size_t o = dbase + (size_t)(nb + ty + j*8)*K + kb + tx;
        hi[o] = h_; lo[o] = l_;
    }
}

// conv weights: w[l][o][i][tap] -> dst[l-block][o][tap*512+i] bf16 hi/lo
__global__ __launch_bounds__(256) void convprep_kernel(
    const float* __restrict__ w, __nv_bfloat16* __restrict__ hi, __nv_bfloat16* __restrict__ lo)
{
    int idx = blockIdx.x * 256 + threadIdx.x;   // 4*512*1536
    int l = idx / (512*1536);
    int r = idx % (512*1536);
    int o = r / 1536;
    int k = r % 1536;
    int tap = k >> 9, i = k & 511;
    float v = w[(((size_t)l*512 + o)*512 + i)*3 + tap];
    __nv_bfloat16 h_, l_; split2(v, h_, l_);
    size_t dst = (size_t)l*LSTRIDE + (size_t)o*1536 + k;
    hi[dst] = h_; lo[dst] = l_;
}

// ---------------- input embedding (also emits bf16 split) ----------------
__global__ __launch_bounds__(256) void embed_kernel(
    const float* __restrict__ x, const float* __restrict__ tf,
    const float* __restrict__ inw, const float* __restrict__ inb,
    const float* __restrict__ pe, const float* __restrict__ tw,
    const float* __restrict__ tb, const float* __restrict__ ps,
    const float* __restrict__ ts, float* __restrict__ out,
    __nv_bfloat16* __restrict__ ohi, __nv_bfloat16* __restrict__ olo)
{
    int bl = blockIdx.x;
    int t  = threadIdx.x;
    __shared__ float xs[64];
    __shared__ float t2[2];
    if (t < 64) xs[t] = x[bl*64 + t];
    if (t < 2)  t2[t] = tf[bl*2 + t];
    __syncthreads();
    float pss = ps[0], tss = ts[0];
    int pos = bl & (NL-1);
    #pragma unroll
    for (int rep = 0; rep < 2; rep++) {
        int d = t + (rep << 8);
        float acc = inb[d];
        #pragma unroll 16
        for (int i = 0; i < 64; i++) acc += xs[i] * inw[i*ND + d];
        acc += pss * pe[pos*ND + d];
        acc += tss * (t2[0]*tw[d] + t2[1]*tw[ND + d] + tb[d]);
        out[bl*ND + d] = acc;
        __nv_bfloat16 h_, l_; split2(acc, h_, l_);
        ohi[bl*ND + d] = h_; olo[bl*ND + d] = l_;
    }
}

// ---------------- HMMA GEMM: 128x64 tile, K-chunks of 64, bf16 3-way split -----------
// 256 threads, 8 warps: wm = wid&3 (32 M-rows), wn = wid>>2 (32 N-cols).
template<int CONV, int RELU, int ADDRES, int OUTF32, int OUTSPLIT>
__device__ __forceinline__ void tgemm_body(
    const __nv_bfloat16* __restrict__ Ahi, const __nv_bfloat16* __restrict__ Alo,
    const __nv_bfloat16* __restrict__ Bhi, const __nv_bfloat16* __restrict__ Blo,
    const float* __restrict__ bias, const float* __restrict__ res,
    float* __restrict__ C, __nv_bfloat16* __restrict__ Chi, __nv_bfloat16* __restrict__ Clo,
    int N, int K, int bn, int bm)
{
    extern __shared__ char smem[];
    uint32_t sb = smem_u32(smem);
    int t = threadIdx.x;
    int lane = t & 31, wid = t >> 5;
    int wm = wid & 3, wn = wid >> 2;

    // ldmatrix per-lane address pieces
    int sub = lane >> 3, r8 = lane & 7;
    uint32_t aOff = (uint32_t)(wm*32 + (sub & 1)*8 + r8) * 144 + (uint32_t)(sub >> 1) * 16;
    uint32_t bOff = (uint32_t)(wn*32 + (sub >> 1)*8 + r8) * 144 + (uint32_t)(sub & 1) * 16;

    float acc[2][4][4];
    #pragma unroll
    for (int i = 0; i < 2; i++)
        #pragma unroll
        for (int j = 0; j < 4; j++)
            #pragma unroll
            for (int q = 0; q < 4; q++) acc[i][j][q] = 0.f;

    int nk = K >> 6;
    for (int c = 0; c < nk; c++) {
        int k0 = c << 6;
        // ---- A tile: 128 rows x 64 bf16; thread loads half a row (32 bf16) ----
        {
            int row = t >> 1, half = t & 1;
            int m = bm + row;
            const uint4* srh; const uint4* srl;
            bool zero = false;
            if (CONV) {
                int tap = k0 >> 9;
                int i0  = (k0 & 511) + half*32;
                zero = ((m & 511) + tap - 2) < 0;
                int rr = m + tap - 2;
                srh = (const uint4*)&Ahi[(size_t)rr*512 + i0];
                srl = (const uint4*)&Alo[(size_t)rr*512 + i0];
            } else {
                srh = (const uint4*)&Ahi[(size_t)m*K + k0 + half*32];
                srl = (const uint4*)&Alo[(size_t)m*K + k0 + half*32];
            }
            uint32_t so = (uint32_t)row*144 + (uint32_t)half*64;
            #pragma unroll
            for (int u = 0; u < 4; u++) {
                uint4 vh, vl;
                if (zero) { vh = make_uint4(0,0,0,0); vl = vh; }
                else      { vh = srh[u]; vl = srl[u]; }
                *(uint4*)(smem + SM_AHI + so + u*16) = vh;
                *(uint4*)(smem + SM_ALO + so + u*16) = vl;
            }
        }
        // ---- B tile: 64 rows x 64 bf16; thread loads quarter row (16 bf16) ----
        {
            int row = t >> 2, q = t & 3;
            const uint4* sh = (const uint4*)&Bhi[(size_t)(bn + row)*K + k0 + q*16];
            const uint4* sl = (const uint4*)&Blo[(size_t)(bn + row)*K + k0 + q*16];
            uint32_t so = (uint32_t)row*144 + (uint32_t)q*32;
            #pragma unroll
            for (int u = 0; u < 2; u++) {
                *(uint4*)(smem + SM_BHI + so + u*16) = sh[u];
                *(uint4*)(smem + SM_BLO + so + u*16) = sl[u];
            }
        }
        __syncthreads();

        #pragma unroll
        for (int ks = 0; ks < 4; ks++) {
            uint32_t ko = ks*32;
            uint32_t ah0[4], ah1[4], al0[4], al1[4];
            uint32_t bh0[4], bh1[4], bl0[4], bl1[4];
            ldsm4(ah0, sb + SM_AHI + aOff + ko);
            ldsm4(ah1, sb + SM_AHI + aOff + 16*144 + ko);
            ldsm4(al0, sb + SM_ALO + aOff + ko);
            ldsm4(al1, sb + SM_ALO + aOff + 16*144 + ko);
            ldsm4(bh0, sb + SM_BHI + bOff + ko);
            ldsm4(bh1, sb + SM_BHI + bOff + 16*144 + ko);
            ldsm4(bl0, sb + SM_BLO + bOff + ko);
            ldsm4(bl1, sb + SM_BLO + bOff + 16*144 + ko);
            #pragma unroll
            for (int mt = 0; mt < 2; mt++) {
                const uint32_t* ah = mt ? ah1 : ah0;
                const uint32_t* al = mt ? al1 : al0;
                #pragma unroll
                for (int nt = 0; nt < 4; nt++) {
                    const uint32_t* bh = ((nt < 2) ? bh0 : bh1) + (nt & 1)*2;
                    const uint32_t* bl = ((nt < 2) ? bl0 : bl1) + (nt & 1)*2;
                    mma16816(acc[mt][nt], ah, bh);
                    mma16816(acc[mt][nt], ah, bl);
                    mma16816(acc[mt][nt], al, bh);
                }
            }
        }
        __syncthreads();
    }

    // ---- epilogue ----
    int g = lane >> 2, tc = lane & 3;
    #pragma unroll
    for (int mt = 0; mt < 2; mt++) {
        #pragma unroll
        for (int h2 = 0; h2 < 2; h2++) {
            int row = bm + wm*32 + mt*16 + h2*8 + g;
            #pragma unroll
            for (int nt = 0; nt < 4; nt++) {
                int col = bn + wn*32 + nt*8 + tc*2;
                float v0 = acc[mt][nt][h2*2+0] + bias[col];
                float v1 = acc[mt][nt][h2*2+1] + bias[col+1];
                if (RELU) { v0 = fmaxf(v0, 0.f); v1 = fmaxf(v1, 0.f); }
                if (ADDRES) {
                    float2 r2 = *(const float2*)&res[(size_t)row*N + col];
                    v0 += r2.x; v1 += r2.y;
                }
                if (OUTF32) {
                    float2 o; o.x = v0; o.y = v1;
                    *(float2*)&C[(size_t)row*N + col] = o;
                }
                if (OUTSPLIT) {
                    __nv_bfloat16 h0, l0, h1, l1;
                    split2(v0, h0, l0);
                    split2(v1, h1, l1);
                    __nv_bfloat162 hp; hp.x = h0; hp.y = h1;
                    __nv_bfloat162 lp; lp.x = l0; lp.y = l1;
                    *(__nv_bfloat162*)&Chi[(size_t)row*N + col] = hp;
                    *(__nv_bfloat162*)&Clo[(size_t)row*N + col] = lp;
                }
            }
        }
    }
}

template<int CONV, int RELU, int ADDRES, int OUTF32, int OUTSPLIT>
__global__ __launch_bounds__(256) void tgemm_kernel(
    const __nv_bfloat16* __restrict__ Ahi, const __nv_bfloat16* __restrict__ Alo,
    const __nv_bfloat16* __restrict__ Bhi, const __nv_bfloat16* __restrict__ Blo,
    const float* __restrict__ bias, const float* __restrict__ res,
    float* __restrict__ C, __nv_bfloat16* __restrict__ Chi, __nv_bfloat16* __restrict__ Clo,
    int N, int K)
{
    tgemm_body<CONV, RELU, ADDRES, OUTF32, OUTSPLIT>(
        Ahi, Alo, Bhi, Blo, bias, res, C, Chi, Clo, N, K,
        blockIdx.x << 6, blockIdx.y << 7);
}

// merged Q/K projection: blockIdx.z in {0,1}; split-only output
__global__ __launch_bounds__(256) void tgemm_qk_kernel(
    const __nv_bfloat16* __restrict__ Ahi, const __nv_bfloat16* __restrict__ Alo,
    const __nv_bfloat16* __restrict__ Whi, const __nv_bfloat16* __restrict__ Wlo,
    const float* __restrict__ b0, const float* __restrict__ b1,
    __nv_bfloat16* __restrict__ q_hi, __nv_bfloat16* __restrict__ q_lo,
    __nv_bfloat16* __restrict__ k_hi, __nv_bfloat16* __restrict__ k_lo)
{
    int z = blockIdx.z;
    const __nv_bfloat16* bh = Whi + (size_t)z * 262144;
    const __nv_bfloat16* bl = Wlo + (size_t)z * 262144;
    const float* bia = (z == 0) ? b0 : b1;
    __nv_bfloat16* chi = (z == 0) ? q_hi : k_hi;
    __nv_bfloat16* clo = (z == 0) ? q_lo : k_lo;
    tgemm_body<0, 0, 0, 0, 1>(Ahi, Alo, bh, bl, bia, nullptr, nullptr, chi, clo,
                              ND, ND, blockIdx.x << 6, blockIdx.y << 7);
}

// ---------------- fused add + LayerNorm (emits fp32 + bf16 split) ----------------
__global__ __launch_bounds__(256) void ln_kernel(
    const float* __restrict__ a, const float* __restrict__ b,
    const float* __restrict__ sc, const float* __restrict__ bi,
    float* __restrict__ out, __nv_bfloat16* __restrict__ ohi, __nv_bfloat16* __restrict__ olo)
{
    int row = blockIdx.x;
    int t = threadIdx.x;
    const float* ar = a + (size_t)row*ND;
    const float* br = b + (size_t)row*ND;
    float v0 = ar[t]       + br[t];
    float v1 = ar[t + 256] + br[t + 256];
    float s1 = v0 + v1;
    float s2 = v0*v0 + v1*v1;
    #pragma unroll
    for (int off = 16; off > 0; off >>= 1) {
        s1 += __shfl_xor_sync(0xffffffffu, s1, off);
        s2 += __shfl_xor_sync(0xffffffffu, s2, off);
    }
    __shared__ float r1[8], r2[8], mv[2];
    int w = t >> 5, lane = t & 31;
    if (lane == 0) { r1[w] = s1; r2[w] = s2; }
    __syncthreads();
    if (t == 0) {
        float a1 = 0.f, a2 = 0.f;
        #pragma unroll
        for (int i = 0; i < 8; i++) { a1 += r1[i]; a2 += r2[i]; }
        float mean = a1 * (1.f/512.f);
        float var  = a2 * (1.f/512.f) - mean*mean;
        mv[0] = mean;
        mv[1] = rsqrtf(var + 1e-5f);
    }
    __syncthreads();
    float mean = mv[0], rstd = mv[1];
    float o0 = (v0 - mean)*rstd*sc[t]       + bi[t];
    float o1 = (v1 - mean)*rstd*sc[t + 256] + bi[t + 256];
    out[(size_t)row*ND + t]       = o0;
    out[(size_t)row*ND + t + 256] = o1;
    __nv_bfloat16 h_, l_;
    split2(o0, h_, l_);
    ohi[(size_t)row*ND + t] = h_;       olo[(size_t)row*ND + t] = l_;
    split2(o1, h_, l_);
    ohi[(size_t)row*ND + t + 256] = h_; olo[(size_t)row*ND + t + 256] = l_;
}

// ---------------- scores (HMMA): per (b,h), lower-tri 64x64 tiles of q @ k^T * scale ----
// Q/K in bf16 hi/lo split; 8 warps as 4(M:16) x 2(N:32).
#define SS_QHI 0
#define SS_QLO 9216
#define SS_KHI 18432
#define SS_KLO 27648
__global__ __launch_bounds__(256) void scores_kernel(
    const __nv_bfloat16* __restrict__ q_hi, const __nv_bfloat16* __restrict__ q_lo,
    const __nv_bfloat16* __restrict__ k_hi, const __nv_bfloat16* __restrict__ k_lo,
    float* __restrict__ sc)
{
    int nt = blockIdx.x, mt = blockIdx.y, bh = blockIdx.z;
    if (nt > mt) return;
    int b = bh >> 3, h = bh & 7;
    __shared__ __align__(16) char ssm[36864];
    uint32_t sb = smem_u32(ssm);
    int t = threadIdx.x;
    int lane = t & 31, wid = t >> 5;
    int wm = wid & 3, wn = wid >> 2;

    // load 64x64 bf16 tiles (hi/lo for q and k); thread t: row=t>>2, quarter=t&3 (16 bf16)
    {
        int row = t >> 2, qq = t & 3;
        size_t qbase = ((size_t)(b*NL + mt*64 + row))*ND + h*HD + qq*16;
        size_t kbase = ((size_t)(b*NL + nt*64 + row))*ND + h*HD + qq*16;
        uint32_t so = (uint32_t)row*144 + (uint32_t)qq*32;
        *(uint4*)(ssm + SS_QHI + so)      = *(const uint4*)&q_hi[qbase];
        *(uint4*)(ssm + SS_QHI + so + 16) = *(const uint4*)&q_hi[qbase + 8];
        *(uint4*)(ssm + SS_QLO + so)      = *(const uint4*)&q_lo[qbase];
        *(uint4*)(ssm + SS_QLO + so + 16) = *(const uint4*)&q_lo[qbase + 8];
        *(uint4*)(ssm + SS_KHI + so)      = *(const uint4*)&k_hi[kbase];
        *(uint4*)(ssm + SS_KHI + so + 16) = *(const uint4*)&k_hi[kbase + 8];
        *(uint4*)(ssm + SS_KLO + so)      = *(const uint4*)&k_lo[kbase];
        *(uint4*)(ssm + SS_KLO + so + 16) = *(const uint4*)&k_lo[kbase + 8];
    }
    __syncthreads();

    int sub = lane >> 3, r8 = lane & 7;
    uint32_t aOff = (uint32_t)(wm*16 + (sub & 1)*8 + r8) * 144 + (uint32_t)(sub >> 1) * 16;
    uint32_t bOff = (uint32_t)(wn*32 + (sub >> 1)*8 + r8) * 144 + (uint32_t)(sub & 1) * 16;

    float acc[4][4];
    #pragma unroll
    for (int j = 0; j < 4; j++)
        #pragma unroll
        for (int qx = 0; qx < 4; qx++) acc[j][qx] = 0.f;

    #pragma unroll
    for (int ks = 0; ks < 4; ks++) {
        uint32_t ko = ks*32;
        uint32_t ah[4], al[4];
        uint32_t bh0[4], bh1[4], bl0[4], bl1[4];
        ldsm4(ah,  sb + SS_QHI + aOff + ko);
        ldsm4(al,  sb + SS_QLO + aOff + ko);
        ldsm4(bh0, sb + SS_KHI + bOff + ko);
        ldsm4(bh1, sb + SS_KHI + bOff + 16*144 + ko);
        ldsm4(bl0, sb + SS_KLO + bOff + ko);
        ldsm4(bl1, sb + SS_KLO + bOff + 16*144 + ko);
        #pragma unroll
        for (int ntf = 0; ntf < 4; ntf++) {
            const uint32_t* bhp = ((ntf < 2) ? bh0 : bh1) + (ntf & 1)*2;
            const uint32_t* blp = ((ntf < 2) ? bl0 : bl1) + (ntf & 1)*2;
            mma16816(acc[ntf], ah, bhp);
            mma16816(acc[ntf], ah, blp);
            mma16816(acc[ntf], al, bhp);
        }
    }

    float* base = sc + (size_t)bh*NL*NL;
    int g = lane >> 2, tc = lane & 3;
    #pragma unroll
    for (int h2 = 0; h2 < 2; h2++) {
        int m = mt*64 + wm*16 + h2*8 + g;
        #pragma unroll
        for (int ntf = 0; ntf < 4; ntf++) {
            int col = nt*64 + wn*32 + ntf*8 + tc*2;
            float2 o;
            o.x = acc[ntf][h2*2+0] * 0.125f;
            o.y = acc[ntf][h2*2+1] * 0.125f;
            *(float2*)&base[(size_t)m*NL + col] = o;
        }
    }
}

// ---------------- top-k(256) select + softmax + P@V (emits ao bf16 split) -----------
__global__ __launch_bounds__(256) void attn_kernel(
    const float* __restrict__ sc, const float* __restrict__ v,
    __nv_bfloat16* __restrict__ aohi, __nv_bfloat16* __restrict__ aolo)
{
    extern __shared__ float sm[];
    float* p  = sm;             // 32*512
    float* vt = sm + 32*512;    // 64*64
    int qt = blockIdx.x, bh = blockIdx.y;
    int b = bh >> 3, h = bh & 7;
    int t = threadIdx.x;

    const float4* s4 = (const float4*)(sc + (size_t)bh*NL*NL + (size_t)(qt*32)*NL);
    float4* p4 = (float4*)p;
    #pragma unroll
    for (int i = 0; i < 16; i++) p4[t + (i << 8)] = s4[t + (i << 8)];
    __syncthreads();

    int w = t >> 5, lane = t & 31;
    for (int rr = 0; rr < 4; rr++) {
        int r  = (w << 2) + rr;
        int qg = (qt << 5) + r;
        int nv = qg + 1;
        float    ev[16];
        unsigned uv[16];
        float    svv[16];
        #pragma unroll
        for (int ii = 0; ii < 16; ii++) {
            int j = lane + (ii << 5);
            bool val = j < nv;
            float s = val ? p[(r << 9) + j] : NEGINF;
            svv[ii] = s;
            unsigned bits = __float_as_uint(s);
            uv[ii] = val ? ((bits & 0x80000000u) ? ~bits : (bits | 0x80000000u)) : 0u;
        }
        unsigned T = 1u;
        if (nv > 256) {
            T = 0u;
            for (int bit = 31; bit >= 0; bit--) {
                unsigned cand = T | (1u << bit);
                int c = 0;
                #pragma unroll
                for (int ii = 0; ii < 16; ii++) c += (uv[ii] >= cand);
                c = __reduce_add_sync(0xffffffffu, c);
                if (c >= 256) T = cand;
            }
        }
        float m = NEGINF;
        #pragma unroll
        for (int ii = 0; ii < 16; ii++)
            if (uv[ii] >= T) m = fmaxf(m, svv[ii]);
        #pragma unroll
        for (int off = 16; off > 0; off >>= 1)
            m = fmaxf(m, __shfl_xor_sync(0xffffffffu, m, off));
        float z = 0.f;
        #pragma unroll
        for (int ii = 0; ii < 16; ii++) {
            float e = (uv[ii] >= T) ? __expf(svv[ii] - m) : 0.f;
            ev[ii] = e;
            z += e;
        }
        #pragma unroll
        for (int off = 16; off > 0; off >>= 1)
            z += __shfl_xor_sync(0xffffffffu, z, off);
        float inv = 1.f / z;
        #pragma unroll
        for (int ii = 0; ii < 16; ii++) {
            int j = lane + (ii << 5);
            p[(r << 9) + j] = ev[ii] * inv;
        }
    }
    __syncthreads();

    float acc[8] = {};
    int d = t & 63, rb = t >> 6;
    for (int jt = 0; jt < 8; jt++) {
        const float4* v4 = (const float4*)(v + ((size_t)(b*NL + (jt << 6)))*ND + (h << 6));
        float4* vt4 = (float4*)vt;
        #pragma unroll
        for (int i = 0; i < 4; i++) {
            int lin = t + (i << 8);
            int jr = lin >> 4, d4 = lin & 15;
            vt4[lin] = v4[(size_t)jr*128 + d4];
        }
        __syncthreads();
        #pragma unroll 2
        for (int j = 0; j < 64; j++) {
            float vv = vt[(j << 6) + d];
            int jj = (jt << 6) + j;
            #pragma unroll
            for (int i = 0; i < 8; i++)
                acc[i] += p[((rb + (i << 2)) << 9) + jj] * vv;
        }
        __syncthreads();
    }
    #pragma unroll
    for (int i = 0; i < 8; i++) {
        int row = (qt << 5) + rb + (i << 2);
        size_t idx = ((size_t)(b*NL + row))*ND + (h << 6) + d;
        __nv_bfloat16 h_, l_;
        split2(acc[i], h_, l_);
        aohi[idx] = h_; aolo[idx] = l_;
    }
}

// ---------------- launch ----------------
extern "C" void kernel_launch(void* const* d_in, const int* in_sizes, int n_in,
                              void* d_out, int out_size) {
    const float* x     = (const float*)d_in[0];
    const float* tf    = (const float*)d_in[1];
    const float* in_w  = (const float*)d_in[2];
    const float* in_b  = (const float*)d_in[3];
    const float* pe    = (const float*)d_in[4];
    const float* tw    = (const float*)d_in[5];
    const float* tb    = (const float*)d_in[6];
    const float* ps    = (const float*)d_in[7];
    const float* ts    = (const float*)d_in[8];
    const float* convw = (const float*)d_in[9];
    const float* convb = (const float*)d_in[10];
    const float* qw    = (const float*)d_in[11];
    const float* qb    = (const float*)d_in[12];
    const float* kw    = (const float*)d_in[13];
    const float* kb    = (const float*)d_in[14];
    const float* vw    = (const float*)d_in[15];
    const float* vb    = (const float*)d_in[16];
    const float* ow    = (const float*)d_in[17];
    const float* ob    = (const float*)d_in[18];
    const float* f1w   = (const float*)d_in[19];
    const float* f1b   = (const float*)d_in[20];
    const float* f2w   = (const float*)d_in[21];
    const float* f2b   = (const float*)d_in[22];
    const float* n1s   = (const float*)d_in[23];
    const float* n1b   = (const float*)d_in[24];
    const float* n2s   = (const float*)d_in[25];
    const float* n2b   = (const float*)d_in[26];

    float *h, *tbuf, *vv, *scb;
    __nv_bfloat16 *whi, *wlo, *hhi, *hlo, *qhi, *qlo, *khi, *klo, *aohi, *aolo, *mhi, *mlo;
    cudaGetSymbolAddress((void**)&h,    g_h);
    cudaGetSymbolAddress((void**)&tbuf, g_t);
    cudaGetSymbolAddress((void**)&vv,   g_v);
    cudaGetSymbolAddress((void**)&scb,  g_sc);
    cudaGetSymbolAddress((void**)&whi,  g_whi);
    cudaGetSymbolAddress((void**)&wlo,  g_wlo);
    cudaGetSymbolAddress((void**)&hhi,  g_hhi);
    cudaGetSymbolAddress((void**)&hlo,  g_hlo);
    cudaGetSymbolAddress((void**)&qhi,  g_qhi);
    cudaGetSymbolAddress((void**)&qlo,  g_qlo);
    cudaGetSymbolAddress((void**)&khi,  g_khi);
    cudaGetSymbolAddress((void**)&klo,  g_klo);
    cudaGetSymbolAddress((void**)&aohi, g_aohi);
    cudaGetSymbolAddress((void**)&aolo, g_aolo);
    cudaGetSymbolAddress((void**)&mhi,  g_mhi);
    cudaGetSymbolAddress((void**)&mlo,  g_mlo);

    cudaFuncSetAttribute(attn_kernel, cudaFuncAttributeMaxDynamicSharedMemorySize, 81920);
    cudaFuncSetAttribute(tgemm_kernel<1,0,0,1,0>, cudaFuncAttributeMaxDynamicSharedMemorySize, SM_SZ);
    cudaFuncSetAttribute(tgemm_kernel<0,0,0,1,0>, cudaFuncAttributeMaxDynamicSharedMemorySize, SM_SZ);
    cudaFuncSetAttribute(tgemm_kernel<0,1,0,0,1>, cudaFuncAttributeMaxDynamicSharedMemorySize, SM_SZ);
    cudaFuncSetAttribute(tgemm_kernel<0,0,1,1,1>, cudaFuncAttributeMaxDynamicSharedMemorySize, SM_SZ);
    cudaFuncSetAttribute(tgemm_kernel<0,0,1,1,0>, cudaFuncAttributeMaxDynamicSharedMemorySize, SM_SZ);
    cudaFuncSetAttribute(tgemm_qk_kernel, cudaFuncAttributeMaxDynamicSharedMemorySize, SM_SZ);

    // ---- weight prep (bf16 split, [N][K]) ----
    convprep_kernel<<<(NE*512*1536)/256, 256>>>(convw, whi, wlo);
    dim3 tb32(32, 8);
    tsplit_kernel<<<dim3(16, 16, 4), tb32>>>(qw,  whi + W_Q,  wlo + W_Q,  512,  512,  262144,  LSTRIDE);
    tsplit_kernel<<<dim3(16, 16, 4), tb32>>>(kw,  whi + W_K,  wlo + W_K,  512,  512,  262144,  LSTRIDE);
    tsplit_kernel<<<dim3(16, 16, 4), tb32>>>(vw,  whi + W_V,  wlo + W_V,  512,  512,  262144,  LSTRIDE);
    tsplit_kernel<<<dim3(16, 16, 4), tb32>>>(ow,  whi + W_O,  wlo + W_O,  512,  512,  262144,  LSTRIDE);
    tsplit_kernel<<<dim3(64, 16, 4), tb32>>>(f1w, whi + W_F1, wlo + W_F1, 512,  2048, 1048576, LSTRIDE);
    tsplit_kernel<<<dim3(16, 64, 4), tb32>>>(f2w, whi + W_F2, wlo + W_F2, 2048, 512,  1048576, LSTRIDE);

    // ---- input embedding ----
    embed_kernel<<<NBL, 256>>>(x, tf, in_w, in_b, pe, tw, tb, ps, ts, h, hhi, hlo);

    dim3 g512(8, 32);         // N=512 tiles
    dim3 gqk (8, 32, 2);
    dim3 gdf (32, 32);        // N=2048 tiles

    for (int l = 0; l < NE; l++) {
        const __nv_bfloat16* lwh = whi + (size_t)l*LSTRIDE;
        const __nv_bfloat16* lwl = wlo + (size_t)l*LSTRIDE;

        // causal conv (K=1536) -> tbuf fp32, then LN1 -> h (+split)
        tgemm_kernel<1,0,0,1,0><<<g512, 256, SM_SZ>>>(
            hhi, hlo, lwh + W_CONV, lwl + W_CONV, convb + l*ND,
            nullptr, tbuf, nullptr, nullptr, ND, 3*ND);
        ln_kernel<<<NBL, 256>>>(h, tbuf, n1s + l*ND, n1b + l*ND, h, hhi, hlo);

        // Q, K projections (split out), V projection (fp32 out)
        tgemm_qk_kernel<<<gqk, 256, SM_SZ>>>(
            hhi, hlo, lwh + W_Q, lwl + W_Q,
            qb + l*ND, kb + l*ND, qhi, qlo, khi, klo);
        tgemm_kernel<0,0,0,1,0><<<g512, 256, SM_SZ>>>(
            hhi, hlo, lwh + W_V, lwl + W_V, vb + l*ND,
            nullptr, vv, nullptr, nullptr, ND, ND);

        // scores (HMMA, lower-triangular tiles only)
        scores_kernel<<<dim3(8, 8, 64), 256>>>(qhi, qlo, khi, klo, scb);

        // top-k select + softmax + P@V -> ao split
        attn_kernel<<<dim3(16, 64), 256, 81920>>>(scb, vv, aohi, aolo);

        // output projection -> tbuf fp32, LN2 -> h (+split)
        tgemm_kernel<0,0,0,1,0><<<g512, 256, SM_SZ>>>(
            aohi, aolo, lwh + W_O, lwl + W_O, ob + l*ND,
            nullptr, tbuf, nullptr, nullptr, ND, ND);
        ln_kernel<<<NBL, 256>>>(h, tbuf, n2s + l*ND, n2b + l*ND, h, hhi, hlo);

        // FFN1: relu, split-only out
        tgemm_kernel<0,1,0,0,1><<<gdf, 256, SM_SZ>>>(
            hhi, hlo, lwh + W_F1, lwl + W_F1, f1b + l*NDF,
            nullptr, nullptr, mhi, mlo, NDF, ND);

        // FFN2: +residual h; fp32 out (+split for next layer's conv)
        if (l < NE-1) {
            tgemm_kernel<0,0,1,1,1><<<g512, 256, SM_SZ>>>(
                mhi, mlo, lwh + W_F2, lwl + W_F2, f2b + l*ND,
                h, h, hhi, hlo, ND, NDF);
        } else {
            tgemm_kernel<0,0,1,1,0><<<g512, 256, SM_SZ>>>(
                mhi, mlo, lwh + W_F2, lwl + W_F2, f2b + l*ND,
                h, (float*)d_out, nullptr, nullptr, ND, NDF);
        }
    }
}